// round 1
// baseline (speedup 1.0000x reference)
#include <cuda_runtime.h>

// NBVLoss: weighted BCE reduction over 16384x4096 fp32 tensors.
//   loss = 1.6 * sum_{t==1} bce + 0.4 * sum_{t==0} bce
//   bce  = -max(log-term, -100), log-term = t ? log(p) : log1p(-p)
// Memory-bound streaming reduction: 536 MB read -> scalar.

#define NBLK 1184   // 148 SMs * 8 blocks (one full resident wave)
#define NTHR 256

__device__ float g_partials[NBLK];

// Weights with ln(2) folded in so the log stays a raw MUFU.LG2.
// contrib = -w * max(ln(x), -100) = (-w*ln2) * max(log2(x), -100/ln2)
#define LN2f 0.693147180559945309f
#define W1P  (-1.6f * LN2f)          // target == 1
#define W0P  (-0.4f * LN2f)          // target == 0
#define CLAMP2 (-100.0f / LN2f)      // -144.269504...

__device__ __forceinline__ float bce_term(float p, float t) {
    bool one = (t != 0.0f);
    float x = one ? p : (1.0f - p);
    float w = one ? W1P : W0P;
    return w * fmaxf(__log2f(x), CLAMP2);
}

__global__ __launch_bounds__(NTHR)
void bce_partial_kernel(const float4* __restrict__ pred4,
                        const float4* __restrict__ targ4,
                        const float* __restrict__ pred,
                        const float* __restrict__ targ,
                        int n4, int n) {
    float acc = 0.0f;
    const int stride = gridDim.x * blockDim.x;
    int i = blockIdx.x * blockDim.x + threadIdx.x;

    for (; i < n4; i += stride) {
        float4 p = pred4[i];
        float4 t = targ4[i];
        acc += bce_term(p.x, t.x);
        acc += bce_term(p.y, t.y);
        acc += bce_term(p.z, t.z);
        acc += bce_term(p.w, t.w);
    }

    // scalar tail (n not divisible by 4) — not hit for this shape, kept for safety
    for (int j = 4 * n4 + blockIdx.x * blockDim.x + threadIdx.x; j < n; j += stride)
        acc += bce_term(pred[j], targ[j]);

    // deterministic block reduction
    __shared__ float s[NTHR];
    s[threadIdx.x] = acc;
    __syncthreads();
#pragma unroll
    for (int o = NTHR / 2; o > 0; o >>= 1) {
        if (threadIdx.x < o) s[threadIdx.x] += s[threadIdx.x + o];
        __syncthreads();
    }
    if (threadIdx.x == 0) g_partials[blockIdx.x] = s[0];
}

__global__ __launch_bounds__(1024)
void final_reduce_kernel(float* __restrict__ out) {
    __shared__ float s[1024];
    float acc = 0.0f;
    for (int i = threadIdx.x; i < NBLK; i += 1024)
        acc += g_partials[i];
    s[threadIdx.x] = acc;
    __syncthreads();
#pragma unroll
    for (int o = 512; o > 0; o >>= 1) {
        if (threadIdx.x < o) s[threadIdx.x] += s[threadIdx.x + o];
        __syncthreads();
    }
    if (threadIdx.x == 0) out[0] = s[0];
}

extern "C" void kernel_launch(void* const* d_in, const int* in_sizes, int n_in,
                              void* d_out, int out_size) {
    const float* pred = (const float*)d_in[0];
    const float* targ = (const float*)d_in[1];
    const int n = in_sizes[0];
    const int n4 = n >> 2;

    bce_partial_kernel<<<NBLK, NTHR>>>(
        (const float4*)pred, (const float4*)targ, pred, targ, n4, n);
    final_reduce_kernel<<<1, 1024>>>((float*)d_out);
}

// round 2
// speedup vs baseline: 1.0039x; 1.0039x over previous
#include <cuda_runtime.h>

// NBVLoss: weighted BCE reduction over 16384x4096 fp32 tensors -> scalar.
// HBM-bound streaming reduction (536 MB read). Single fused kernel:
// grid-stride stream + per-block partial + last-block final reduce.

#define NBLK 1184   // 148 SMs * 8 resident blocks (one full wave)
#define NTHR 256
#define NWARP (NTHR / 32)

__device__ float g_partials[NBLK];
__device__ unsigned int g_ticket = 0;   // reset to 0 by last block each run

// Fold ln(2) into weights so the log stays a single MUFU.LG2:
// contrib = -w * max(ln(x), -100) = (-w*ln2) * max(log2(x), -100/ln2)
#define LN2f 0.693147180559945309f
#define W1P  (-1.6f * LN2f)          // target == 1
#define W0P  (-0.4f * LN2f)          // target == 0
#define CLAMP2 (-100.0f / LN2f)

__device__ __forceinline__ float bce_term(float p, float t) {
    bool one = (t != 0.0f);
    float x = one ? p : (1.0f - p);
    float w = one ? W1P : W0P;
    return w * fmaxf(__log2f(x), CLAMP2);
}

__device__ __forceinline__ float warp_sum(float v) {
#pragma unroll
    for (int o = 16; o > 0; o >>= 1)
        v += __shfl_down_sync(0xFFFFFFFFu, v, o);
    return v;
}

__global__ __launch_bounds__(NTHR)
void bce_fused_kernel(const float4* __restrict__ pred4,
                      const float4* __restrict__ targ4,
                      const float* __restrict__ pred,
                      const float* __restrict__ targ,
                      int n4, int n,
                      float* __restrict__ out) {
    float acc = 0.0f;
    const int stride = gridDim.x * blockDim.x;
    int i = blockIdx.x * blockDim.x + threadIdx.x;

    for (; i < n4; i += stride) {
        float4 p = pred4[i];
        float4 t = targ4[i];
        acc += bce_term(p.x, t.x);
        acc += bce_term(p.y, t.y);
        acc += bce_term(p.z, t.z);
        acc += bce_term(p.w, t.w);
    }

    // scalar tail (unused for this shape, kept for safety)
    for (int j = 4 * n4 + blockIdx.x * blockDim.x + threadIdx.x; j < n; j += stride)
        acc += bce_term(pred[j], targ[j]);

    // ---- block reduction (warp shuffle + one smem pass) ----
    __shared__ float s_warp[NWARP];
    const int lane = threadIdx.x & 31;
    const int wid  = threadIdx.x >> 5;

    acc = warp_sum(acc);
    if (lane == 0) s_warp[wid] = acc;
    __syncthreads();

    if (wid == 0) {
        float v = (lane < NWARP) ? s_warp[lane] : 0.0f;
        v = warp_sum(v);
        if (lane == 0) g_partials[blockIdx.x] = v;
    }

    // ---- last-block final reduce (deterministic: fixed-order read) ----
    __shared__ bool s_last;
    if (threadIdx.x == 0) {
        __threadfence();  // make g_partials[blockIdx.x] globally visible
        unsigned int t = atomicAdd(&g_ticket, 1u);
        s_last = (t == (unsigned int)(gridDim.x - 1));
    }
    __syncthreads();

    if (s_last) {
        float v = 0.0f;
        for (int k = threadIdx.x; k < NBLK; k += NTHR)
            v += g_partials[k];
        v = warp_sum(v);
        if (lane == 0) s_warp[wid] = v;
        __syncthreads();
        if (wid == 0) {
            float r = (lane < NWARP) ? s_warp[lane] : 0.0f;
            r = warp_sum(r);
            if (lane == 0) {
                out[0] = r;
                g_ticket = 0;   // reset for next (graph-replayed) run
            }
        }
    }
}

extern "C" void kernel_launch(void* const* d_in, const int* in_sizes, int n_in,
                              void* d_out, int out_size) {
    const float* pred = (const float*)d_in[0];
    const float* targ = (const float*)d_in[1];
    const int n = in_sizes[0];
    const int n4 = n >> 2;

    bce_fused_kernel<<<NBLK, NTHR>>>(
        (const float4*)pred, (const float4*)targ, pred, targ, n4, n,
        (float*)d_out);
}